// round 15
// baseline (speedup 1.0000x reference)
#include <cuda_runtime.h>
#include <cuda_bf16.h>
#include <math.h>

#define N_ROWS 131072
#define DIM 64
#define K_EMB 1024

// Output layout (tuple order: quantized_st, quantized_original, perplexity, encodings)
#define OFF_QST   0
#define OFF_QORIG 8388608
#define OFF_PERP  16777216
#define OFF_ENC   16777217
#define ENC_COUNT ((size_t)N_ROWS * K_EMB)

__device__ int   g_idx[N_ROWS];
__device__ float g_b32[K_EMB];
__device__ int   g_counts[K_EMB];
__device__ int   g_flagged[N_ROWS];
__device__ int   g_nflag;
// embeddings, two-level int8, pre-swizzled: 128 B per code row, 8 chunks of
// 16B: chunks 0-3 = eh8, chunks 4-7 = el8 (e = (eh8 + el8/128)/(1024*127),
// exact to ~3e-8). The k-loop aliases chunks to realize [xh,xl,xh].[eh,eh,el].
__device__ uint4 g_e_swz[8192];            // 1024 rows x 128 B
// candidate pool: per row 8 float4 = 16 (d, idx) candidates
__device__ float4 g_part[(size_t)N_ROWS * 8];

// ---------------------------------------------------------------------------
// helpers
// ---------------------------------------------------------------------------
__device__ __forceinline__ unsigned smem_u32(const void* p) {
    unsigned a;
    asm("{ .reg .u64 t; cvta.to.shared.u64 t, %1; cvt.u32.u64 %0, t; }"
        : "=r"(a) : "l"(p));
    return a;
}
__device__ __forceinline__ void ldsm4(unsigned* r, unsigned addr) {
    asm volatile("ldmatrix.sync.aligned.m8n8.x4.shared.b16 {%0,%1,%2,%3}, [%4];"
                 : "=r"(r[0]), "=r"(r[1]), "=r"(r[2]), "=r"(r[3]) : "r"(addr));
}
// s8 k32 mma: fragment byte-layout identical to bf16 k16 (16 rows x 32 B),
// so ldmatrix addressing is unchanged; accumulators are exact int32.
__device__ __forceinline__ void mma_s8(int* d, const unsigned* a, const unsigned* b) {
    asm volatile(
        "mma.sync.aligned.m16n8k32.row.col.s32.s8.s8.s32 "
        "{%0,%1,%2,%3}, {%4,%5,%6,%7}, {%8,%9}, {%0,%1,%2,%3};"
        : "+r"(d[0]), "+r"(d[1]), "+r"(d[2]), "+r"(d[3])
        : "r"(a[0]), "r"(a[1]), "r"(a[2]), "r"(a[3]), "r"(b[0]), "r"(b[1]));
}
__device__ __forceinline__ void cp_async16(unsigned dst, const void* src) {
    asm volatile("cp.async.cg.shared.global [%0], [%1], 16;"
                 :: "r"(dst), "l"(src));
}
#define CP_COMMIT() asm volatile("cp.async.commit_group;" ::: "memory")
#define CP_WAIT0()  asm volatile("cp.async.wait_group 0;" ::: "memory")

// swizzled byte offset within a (rows x 8-chunk) tile (chunk = 16B, 128B/row)
#define SWZ8(r, c) ((r) * 128 + ((((c) ^ ((r) & 7)) & 7) << 4))

// ---------------------------------------------------------------------------
// Convert embeddings -> pre-swizzled two-level int8 [eh | el]; b32 = exact
// fp32 ||e||^2; zero counts/nflag. One warp per code row.
// ---------------------------------------------------------------------------
__global__ void vq_convert_emb(const float* __restrict__ emb) {
    int lane = threadIdx.x & 31;
    int row  = (blockIdx.x * blockDim.x + threadIdx.x) >> 5;
    if (blockIdx.x == 0 && threadIdx.x == 0) g_nflag = 0;
    if (row >= K_EMB) return;

    float2 v = ((const float2*)(emb + (size_t)row * DIM))[lane];
    // e in (-1/1024, 1/1024): e*130048 in (-127, 127) — fits s8 exactly
    float t0 = v.x * 130048.0f;              // 1024*127
    int   h0 = __float2int_rn(t0);
    int   l0 = __float2int_rn((t0 - (float)h0) * 128.0f);
    float t1 = v.y * 130048.0f;
    int   h1 = __float2int_rn(t1);
    int   l1 = __float2int_rn((t1 - (float)h1) * 128.0f);
    unsigned short hp = (unsigned short)((h0 & 0xff) | ((h1 & 0xff) << 8));
    unsigned short lp = (unsigned short)((l0 & 0xff) | ((l1 & 0xff) << 8));

    int tile = row >> 7, r = row & 127;
    unsigned char* tb = (unsigned char*)g_e_swz + tile * 16384;
    int c   = lane >> 3;                     // chunk = (2*lane)/16
    int pos = (2 * lane) & 15;               // byte within chunk
    *(unsigned short*)(tb + SWZ8(r, c)     + pos) = hp;   // eh chunks 0-3
    *(unsigned short*)(tb + SWZ8(r, 4 + c) + pos) = lp;   // el chunks 4-7

    double s = (double)v.x * v.x + (double)v.y * v.y;
    #pragma unroll
    for (int off = 16; off > 0; off >>= 1)
        s += __shfl_down_sync(0xffffffffu, s, off);
    if (lane == 0) { g_b32[row] = (float)s; g_counts[row] = 0; }
}

// ---------------------------------------------------------------------------
// Fused convert-x + INT8 MMA distance + top-2 + combine + flag + histogram +
// OUTPUT WRITES. CTA = 128 rows; warps 4x2: wm (32 rows) x wn (64 codes),
// processed in 16-code quarters (two int acc groups of 16 regs each).
// x quantized per-row two-level int8 in phase 0 (scale ax/127).
// m = itot * ax/(127*127*1024*128), itot = 128*acc1 + acc2 (exact int32).
// 6 k32-steps alias blocks: A [xh,xl,xh], B [eh,eh,el].
// SMEM: bs[1024]f @0, a32s @4096, sm2 @4608, A @5120 (16KB),
//       B0 @21504 (16KB), B1 @37888 (16KB). Total 54272.
// ---------------------------------------------------------------------------
#define SM_A  5120
#define SM_B0 21504
#define SM_B1 37888
#define SM_TOTAL 54272

__global__ __launch_bounds__(256, 2) void vq_mma(const float* __restrict__ xall,
                                                 const float* __restrict__ emb,
                                                 float* __restrict__ out) {
    extern __shared__ char smem[];
    float* bs   = (float*)smem;
    float* a32s = (float*)(smem + 4096);
    float* sm2  = (float*)(smem + 4608);
    unsigned sbase = smem_u32(smem);
    int tid  = threadIdx.x;
    int wid  = tid >> 5;
    int lane = tid & 31;
    int l7   = lane & 7;
    int wm   = wid & 3;       // 4 row-groups of 32
    int wn   = wid >> 2;      // 2 code-halves of 64
    int mtile = blockIdx.x;

    // prefetch ntile 0 into B0 (1024 uint4 = 16KB)
    {
        const uint4* src = g_e_swz;
        #pragma unroll
        for (int u = 0; u < 4; u++) {
            int i = u * 256 + tid;
            cp_async16(sbase + SM_B0 + i * 16, src + i);
        }
        CP_COMMIT();
    }

    // Phase 0: bs fill + x quantize to [xh8 | xl8] + a32 + per-row scale
    for (int i = tid; i < K_EMB; i += 256) bs[i] = g_b32[i];
    {
        int r = tid >> 1, h = tid & 1;
        const float4* xr = (const float4*)(xall + ((size_t)(mtile * 128 + r)) * DIM + h * 32);
        float vals[32];
        double ss = 0.0;
        float mx = 1e-20f;
        #pragma unroll
        for (int j = 0; j < 8; j++) {
            float4 f = xr[j];
            vals[4*j+0] = f.x; vals[4*j+1] = f.y;
            vals[4*j+2] = f.z; vals[4*j+3] = f.w;
            ss += (double)f.x * f.x + (double)f.y * f.y
                + (double)f.z * f.z + (double)f.w * f.w;
            mx = fmaxf(mx, fmaxf(fmaxf(fabsf(f.x), fabsf(f.y)),
                                 fmaxf(fabsf(f.z), fabsf(f.w))));
        }
        mx = fmaxf(mx, __shfl_xor_sync(0xffffffffu, mx, 1));
        ss += __shfl_xor_sync(0xffffffffu, ss, 1);
        if (h == 0) {
            a32s[r] = (float)ss;
            // 2 * ax / (127*127*1024*128); the 2 folds the distance formula
            sm2[r]  = 2.0f * mx / 2114060288.0f;
        }
        float inv = 127.0f / mx;
        unsigned xh[8], xl[8];
        #pragma unroll
        for (int w = 0; w < 8; w++) {
            unsigned hu = 0, lu = 0;
            #pragma unroll
            for (int b = 0; b < 4; b++) {
                float t = vals[w * 4 + b] * inv;       // in [-127, 127]
                int hq = __float2int_rn(t);
                int lq = __float2int_rn((t - (float)hq) * 128.0f);  // [-64,64]
                hu |= (unsigned)(hq & 0xff) << (8 * b);
                lu |= (unsigned)(lq & 0xff) << (8 * b);
            }
            xh[w] = hu; xl[w] = lu;
        }
        // values h*32+v -> xh chunks 2h,2h+1 ; xl chunks 4+2h,4+2h+1
        *(uint4*)(smem + SM_A + SWZ8(r, 2*h))     = make_uint4(xh[0], xh[1], xh[2], xh[3]);
        *(uint4*)(smem + SM_A + SWZ8(r, 2*h + 1)) = make_uint4(xh[4], xh[5], xh[6], xh[7]);
        *(uint4*)(smem + SM_A + SWZ8(r, 4 + 2*h))     = make_uint4(xl[0], xl[1], xl[2], xl[3]);
        *(uint4*)(smem + SM_A + SWZ8(r, 4 + 2*h + 1)) = make_uint4(xl[4], xl[5], xl[6], xl[7]);
    }

    // ldmatrix base addresses (128 B rows)
    int a_sub = ((lane >> 3) & 1) * 8 + l7;
    int a_ch  = (lane >> 4) & 1;
    unsigned abase0 = sbase + SM_A + (wm * 32 + a_sub) * 128;
    unsigned abase1 = abase0 + 16 * 128;
    int b_sub = ((lane >> 4) & 1) * 8 + l7;
    int b_ch  = (lane >> 3) & 1;

    int q    = lane >> 2;       // row-within-8 owner
    int cpos = (lane & 3) * 2;  // col pair within n8

    CP_WAIT0();
    __syncthreads();

    float a32r[4], sm2r[4];
    #pragma unroll
    for (int m = 0; m < 4; m++) {
        a32r[m] = a32s[wm * 32 + q + m * 8];
        sm2r[m] = sm2 [wm * 32 + q + m * 8];
    }

    float d1[4], d2[4];
    int   i1[4], i2[4];
    #pragma unroll
    for (int m = 0; m < 4; m++) { d1[m] = 3.4e38f; d2[m] = 3.4e38f; i1[m] = 0; i2[m] = 0; }

    for (int nt = 0; nt < 8; nt++) {
        unsigned bcur = sbase + ((nt & 1) ? SM_B1 : SM_B0);
        if (nt < 7) {
            unsigned bnext = sbase + ((nt & 1) ? SM_B0 : SM_B1);
            const uint4* src = g_e_swz + (nt + 1) * 1024;
            #pragma unroll
            for (int u = 0; u < 4; u++) {
                int i = u * 256 + tid;
                cp_async16(bnext + i * 16, src + i);
            }
            CP_COMMIT();
        }

        #pragma unroll
        for (int quarter = 0; quarter < 4; quarter++) {
            unsigned bq = bcur + (unsigned)((wn * 64 + quarter * 16 + b_sub) * 128);

            int acc1[2][2][4], acc2[2][2][4];
            #pragma unroll
            for (int t = 0; t < 2; t++)
                #pragma unroll
                for (int j = 0; j < 2; j++)
                    #pragma unroll
                    for (int e4 = 0; e4 < 4; e4++) {
                        acc1[t][j][e4] = 0; acc2[t][j][e4] = 0;
                    }

            #pragma unroll
            for (int ks = 0; ks < 6; ks++) {
                // A alias: ks 0-1 -> xh (chunks 0-3), 2-3 -> xl (4-7), 4-5 -> xh
                int pa = (ks < 4) ? ks : ks - 4;
                int ca = 2 * pa + a_ch;
                unsigned aoff = (((ca ^ l7) & 7) << 4);
                unsigned af0[4], af1[4];
                ldsm4(af0, abase0 + aoff);
                ldsm4(af1, abase1 + aoff);
                // B alias: ks 0-1 -> eh (chunks 0-3), 2-3 -> eh, 4-5 -> el (4-7)
                int pb = (ks < 2) ? ks : ks - 2;
                int cb = 2 * pb + b_ch;
                unsigned boff = (((cb ^ l7) & 7) << 4);
                unsigned bf[4];
                ldsm4(bf, bq + boff);
                if (ks < 2) {                 // xh.eh : weight 1
                    mma_s8(acc1[0][0], af0, bf);
                    mma_s8(acc1[0][1], af0, bf + 2);
                    mma_s8(acc1[1][0], af1, bf);
                    mma_s8(acc1[1][1], af1, bf + 2);
                } else {                      // xl.eh + xh.el : weight 1/128
                    mma_s8(acc2[0][0], af0, bf);
                    mma_s8(acc2[0][1], af0, bf + 2);
                    mma_s8(acc2[1][0], af1, bf);
                    mma_s8(acc2[1][1], af1, bf + 2);
                }
            }

            // epilogue: itot = 128*acc1 + acc2 (exact); d = fl(a32+b) - itot*sm2
            int colbase = nt * 128 + wn * 64 + quarter * 16;
            #pragma unroll
            for (int j = 0; j < 2; j++) {
                float2 bv = *(float2*)&bs[colbase + j * 8 + cpos];
                int k0 = colbase + j * 8 + cpos;
                #pragma unroll
                for (int t = 0; t < 2; t++) {
                    #pragma unroll
                    for (int rr = 0; rr < 2; rr++) {
                        int m = t * 2 + rr;
                        float ta = a32r[m];
                        int it0 = acc1[t][j][2*rr]     * 128 + acc2[t][j][2*rr];
                        int it1 = acc1[t][j][2*rr + 1] * 128 + acc2[t][j][2*rr + 1];
                        float v0 = fmaf((float)it0, -sm2r[m], __fadd_rn(ta, bv.x));
                        float v1 = fmaf((float)it1, -sm2r[m], __fadd_rn(ta, bv.y));
                        if (v0 < d2[m]) {
                            if (v0 < d1[m]) { d2[m] = d1[m]; i2[m] = i1[m];
                                              d1[m] = v0;    i1[m] = k0; }
                            else            { d2[m] = v0;    i2[m] = k0; }
                        }
                        if (v1 < d2[m]) {
                            if (v1 < d1[m]) { d2[m] = d1[m]; i2[m] = i1[m];
                                              d1[m] = v1;    i1[m] = k0 + 1; }
                            else            { d2[m] = v1;    i2[m] = k0 + 1; }
                        }
                    }
                }
            }
        }
        CP_WAIT0();
        __syncthreads();
    }

    // candidate pool: per lane, per row: (d1,d2,i1,i2)
    #pragma unroll
    for (int m = 0; m < 4; m++) {
        int row = mtile * 128 + wm * 32 + q + m * 8;
        g_part[(size_t)row * 8 + wn * 4 + (lane & 3)] =
            make_float4(d1[m], d2[m], __int_as_float(i1[m]), __int_as_float(i2[m]));
    }

    // quad merge (lanes sharing a row); lowest-index tie-break
    #pragma unroll
    for (int off = 1; off <= 2; off <<= 1) {
        #pragma unroll
        for (int m = 0; m < 4; m++) {
            float od1 = __shfl_xor_sync(0xffffffffu, d1[m], off);
            int   oi1 = __shfl_xor_sync(0xffffffffu, i1[m], off);
            float od2 = __shfl_xor_sync(0xffffffffu, d2[m], off);
            int   oi2 = __shfl_xor_sync(0xffffffffu, i2[m], off);
            if (od1 < d1[m] || (od1 == d1[m] && oi1 < i1[m])) {
                float t = d1[m]; int ti = i1[m];
                d1[m] = od1; i1[m] = oi1;
                if (od2 < t || (od2 == t && oi2 < ti)) { d2[m] = od2; i2[m] = oi2; }
                else                                   { d2[m] = t;   i2[m] = ti; }
            } else if (od1 < d2[m] || (od1 == d2[m] && oi1 < i2[m])) {
                d2[m] = od1; i2[m] = oi1;
            }
        }
    }

    // cross-half merge via smem (reuse B0 region); winners into sIdx;
    // provisional histogram (fixed up by vq_exact on flips)
    __syncthreads();
    float* md1  = (float*)(smem + SM_B0);
    float* md2  = (float*)(smem + SM_B0 + 512);
    int*   mi1  = (int*)  (smem + SM_B0 + 1024);
    int*   sIdx = (int*)  (smem + 4096);
    if (wn == 0 && (lane & 3) == 0) {
        #pragma unroll
        for (int m = 0; m < 4; m++) {
            int rl = wm * 32 + q + m * 8;
            md1[rl] = d1[m]; md2[rl] = d2[m]; mi1[rl] = i1[m];
        }
    }
    __syncthreads();
    if (wn == 1 && (lane & 3) == 0) {
        #pragma unroll
        for (int m = 0; m < 4; m++) {
            int rl  = wm * 32 + q + m * 8;
            int row = mtile * 128 + rl;
            float oa = md1[rl], oa2 = md2[rl];
            int   ia = mi1[rl];
            float D1, D2; int I1;
            if (d1[m] < oa) { D1 = d1[m]; I1 = i1[m]; D2 = fminf(oa, d2[m]); }
            else            { D1 = oa;    I1 = ia;    D2 = fminf(d1[m], oa2); }
            g_idx[row] = I1;
            sIdx[rl]   = I1;
            atomicAdd(&g_counts[I1], 1);
            float thr = a32r[m] * 9.536743e-7f;   // 8 * 2^-23 * a32
            if (!((D2 - D1) > thr)) {
                int pos = atomicAdd(&g_nflag, 1);
                if (pos < N_ROWS) g_flagged[pos] = row;
            }
        }
    }
    __syncthreads();

    // Fused output writes: warp w handles rows [16w, 16w+16) of this mtile.
    // st = fl(x + fl(q - x)), qorig = emb[idx], one-hot row. Streaming stores.
    #pragma unroll 1
    for (int rr = 0; rr < 16; rr++) {
        int rl  = wid * 16 + rr;
        int row = mtile * 128 + rl;
        int idx = sIdx[rl];
        float2 qv = ((const float2*)(emb  + (size_t)idx * DIM))[lane];
        float2 xv = ((const float2*)(xall + (size_t)row * DIM))[lane];
        float2 st;
        st.x = __fadd_rn(xv.x, __fadd_rn(qv.x, -xv.x));
        st.y = __fadd_rn(xv.y, __fadd_rn(qv.y, -xv.y));
        __stcs((float2*)(out + OFF_QST   + (size_t)row * DIM) + lane, st);
        __stcs((float2*)(out + OFF_QORIG + (size_t)row * DIM) + lane, qv);

        float* er = out + OFF_ENC + (size_t)row * K_EMB;
        if (lane < 3) __stcs(er + lane, (lane == idx) ? 1.0f : 0.0f);
        if (lane == 3) __stcs(er + 1023, (idx == 1023) ? 1.0f : 0.0f);
        float4* body = (float4*)(er + 3);   // 16B-aligned
        #pragma unroll
        for (int u = 0; u < 8; u++) {
            int i = u * 32 + lane;
            if (i < 255) {
                int k0 = 3 + i * 4;
                float4 v;
                v.x = (k0     == idx) ? 1.0f : 0.0f;
                v.y = (k0 + 1 == idx) ? 1.0f : 0.0f;
                v.z = (k0 + 2 == idx) ? 1.0f : 0.0f;
                v.w = (k0 + 3 == idx) ? 1.0f : 0.0f;
                __stcs(body + i, v);
            }
        }
    }
}

// ---------------------------------------------------------------------------
// Exact re-rank of flagged rows over the 16 pooled candidates; if the winner
// changes, fix g_idx, the histogram, AND the already-written outputs.
// ---------------------------------------------------------------------------
__global__ __launch_bounds__(256)
void vq_exact(const float* __restrict__ xall, const float* __restrict__ emb,
              float* __restrict__ out) {
    int nf = g_nflag;
    if (nf > N_ROWS) nf = N_ROWS;
    int lane  = threadIdx.x & 31;
    int warp  = (blockIdx.x * blockDim.x + threadIdx.x) >> 5;
    int nwarp = (gridDim.x * blockDim.x) >> 5;

    for (int f = warp; f < nf; f += nwarp) {
        int row  = g_flagged[f];
        int oldi = g_idx[row];
        float bestd = 3.4e38f;
        int   besti = 0x7fffffff;
        if (lane < 16) {
            float4 qq = g_part[(size_t)row * 8 + (lane >> 1)];
            int k = (lane & 1) ? __float_as_int(qq.w) : __float_as_int(qq.z);
            const float* x = xall + (size_t)row * DIM;
            const float* e = emb  + (size_t)k * DIM;
            double ad = 0.0;
            float s = 0.f, c = 0.f;
            #pragma unroll
            for (int j = 0; j < DIM; j++) {
                float xv = __ldg(x + j), ev = __ldg(e + j);
                ad += (double)xv * (double)xv;
                float pr = __fmul_rn(xv, ev);
                float pe = fmaf(xv, ev, -pr);
                float t  = __fadd_rn(s, pr);
                float z  = __fadd_rn(t, -s);
                float se = __fadd_rn(__fadd_rn(s, -__fadd_rn(t, -z)),
                                     __fadd_rn(pr, -z));
                s = t;
                c = __fadd_rn(c, __fadd_rn(pe, se));
            }
            float a32 = (float)ad;
            float m  = __fadd_rn(s, c);
            float t2 = __fadd_rn(a32, g_b32[k]);
            bestd = __fadd_rn(t2, -__fmul_rn(2.0f, m));
            besti = k;
        }
        #pragma unroll
        for (int off = 8; off > 0; off >>= 1) {
            float od = __shfl_down_sync(0xffffffffu, bestd, off);
            int   oi = __shfl_down_sync(0xffffffffu, besti, off);
            if (od < bestd || (od == bestd && oi < besti)) { bestd = od; besti = oi; }
        }
        besti = __shfl_sync(0xffffffffu, besti, 0);

        if (besti != oldi) {
            if (lane == 0) {
                g_idx[row] = besti;
                atomicSub(&g_counts[oldi], 1);
                atomicAdd(&g_counts[besti], 1);
            }
            // fix st / qorig
            float2 qv = ((const float2*)(emb  + (size_t)besti * DIM))[lane];
            float2 xv = ((const float2*)(xall + (size_t)row  * DIM))[lane];
            float2 st;
            st.x = __fadd_rn(xv.x, __fadd_rn(qv.x, -xv.x));
            st.y = __fadd_rn(xv.y, __fadd_rn(qv.y, -xv.y));
            ((float2*)(out + OFF_QST   + (size_t)row * DIM))[lane] = st;
            ((float2*)(out + OFF_QORIG + (size_t)row * DIM))[lane] = qv;
            // fix one-hot
            if (lane == 0) {
                out[OFF_ENC + (size_t)row * K_EMB + oldi]  = 0.0f;
                out[OFF_ENC + (size_t)row * K_EMB + besti] = 1.0f;
            }
        }
    }
}

// ---------------------------------------------------------------------------
// Perplexity in fp32 (reference computes in fp32; MUFU logf/expf, not DFMA).
// ---------------------------------------------------------------------------
__global__ void vq_perplexity(float* __restrict__ out) {
    __shared__ float s[256];
    float local = 0.0f;
    for (int k = threadIdx.x; k < K_EMB; k += 256) {
        float p = (float)g_counts[k] * (1.0f / 131072.0f);
        local += p * logf(p + 1e-10f);
    }
    s[threadIdx.x] = local;
    __syncthreads();
    for (int off = 128; off > 0; off >>= 1) {
        if (threadIdx.x < off) s[threadIdx.x] += s[threadIdx.x + off];
        __syncthreads();
    }
    if (threadIdx.x == 0) out[OFF_PERP] = expf(-s[0]);
}

// ---------------------------------------------------------------------------
extern "C" void kernel_launch(void* const* d_in, const int* in_sizes, int n_in,
                              void* d_out, int out_size) {
    const float* x   = (const float*)d_in[0];
    const float* emb = (const float*)d_in[1];
    float* out = (float*)d_out;

    cudaFuncSetAttribute(vq_mma, cudaFuncAttributeMaxDynamicSharedMemorySize, SM_TOTAL);

    vq_convert_emb<<<128, 256>>>(emb);
    vq_mma<<<1024, 256, SM_TOTAL>>>(x, emb, out);
    vq_exact<<<256, 256>>>(x, emb, out);
    vq_perplexity<<<1, 256>>>(out);
}

// round 16
// speedup vs baseline: 1.6734x; 1.6734x over previous
#include <cuda_runtime.h>
#include <cuda_bf16.h>
#include <math.h>

#define N_ROWS 131072
#define DIM 64
#define K_EMB 1024

// Output layout (tuple order: quantized_st, quantized_original, perplexity, encodings)
#define OFF_QST   0
#define OFF_QORIG 8388608
#define OFF_PERP  16777216
#define OFF_ENC   16777217
#define ENC_COUNT ((size_t)N_ROWS * K_EMB)

__device__ int   g_idx[N_ROWS];
__device__ float g_b32[K_EMB];
__device__ int   g_counts[K_EMB];
__device__ int   g_flagged[N_ROWS];
__device__ int   g_nflag;
// embeddings, bf16-split, pre-swizzled: per code row 16 chunks of 16B:
// chunks 0-7 = eh, chunks 8-15 = el. (The duplicated eh block of the K=192
// concat is realized by address aliasing in the MMA k-loop, not by storage.)
__device__ uint4 g_e_swz[16384];           // 1024 rows x 256 B
// candidate pool: per row 8 float4 = 16 (d, idx) candidates
__device__ float4 g_part[(size_t)N_ROWS * 8];

// ---------------------------------------------------------------------------
// helpers
// ---------------------------------------------------------------------------
__device__ __forceinline__ unsigned smem_u32(const void* p) {
    unsigned a;
    asm("{ .reg .u64 t; cvta.to.shared.u64 t, %1; cvt.u32.u64 %0, t; }"
        : "=r"(a) : "l"(p));
    return a;
}
__device__ __forceinline__ void ldsm4(unsigned* r, unsigned addr) {
    asm volatile("ldmatrix.sync.aligned.m8n8.x4.shared.b16 {%0,%1,%2,%3}, [%4];"
                 : "=r"(r[0]), "=r"(r[1]), "=r"(r[2]), "=r"(r[3]) : "r"(addr));
}
__device__ __forceinline__ void mma_bf16(float* d, const unsigned* a, const unsigned* b) {
    asm volatile(
        "mma.sync.aligned.m16n8k16.row.col.f32.bf16.bf16.f32 "
        "{%0,%1,%2,%3}, {%4,%5,%6,%7}, {%8,%9}, {%0,%1,%2,%3};"
        : "+f"(d[0]), "+f"(d[1]), "+f"(d[2]), "+f"(d[3])
        : "r"(a[0]), "r"(a[1]), "r"(a[2]), "r"(a[3]), "r"(b[0]), "r"(b[1]));
}
__device__ __forceinline__ void cp_async16(unsigned dst, const void* src) {
    asm volatile("cp.async.cg.shared.global [%0], [%1], 16;"
                 :: "r"(dst), "l"(src));
}
#define CP_COMMIT() asm volatile("cp.async.commit_group;" ::: "memory")
#define CP_WAIT0()  asm volatile("cp.async.wait_group 0;" ::: "memory")

// pack two floats' bf16-high parts into one u32; also produce residual pack
__device__ __forceinline__ void split2(float x, float y, unsigned& hp, unsigned& lp) {
    __nv_bfloat16 hx = __float2bfloat16_rn(x);
    __nv_bfloat16 hy = __float2bfloat16_rn(y);
    __nv_bfloat16 lx = __float2bfloat16_rn(__fadd_rn(x, -__bfloat162float(hx)));
    __nv_bfloat16 ly = __float2bfloat16_rn(__fadd_rn(y, -__bfloat162float(hy)));
    hp = ((unsigned)__bfloat16_as_ushort(hy) << 16) | __bfloat16_as_ushort(hx);
    lp = ((unsigned)__bfloat16_as_ushort(ly) << 16) | __bfloat16_as_ushort(lx);
}

// swizzled byte offset within a 128-row x 16-chunk tile (chunk = 16B, 256B/row)
#define SWZ16(r, c) ((r) * 256 + ((((c) & 8) | (((c) & 7) ^ ((r) & 7))) << 4))

// ---------------------------------------------------------------------------
// Convert embeddings -> pre-swizzled bf16-split tiles [eh | el]; b32;
// zero counts/nflag. One warp per code row.
// ---------------------------------------------------------------------------
__global__ void vq_convert_emb(const float* __restrict__ emb) {
    int lane = threadIdx.x & 31;
    int row  = (blockIdx.x * blockDim.x + threadIdx.x) >> 5;
    if (blockIdx.x == 0 && threadIdx.x == 0) g_nflag = 0;
    if (row >= K_EMB) return;

    float2 v = ((const float2*)(emb + (size_t)row * DIM))[lane];
    unsigned hp, lp;
    split2(v.x, v.y, hp, lp);
    int tile = row >> 7, r = row & 127;
    unsigned char* tb = (unsigned char*)g_e_swz + tile * 32768;
    int c   = lane >> 2;
    int pos = (lane & 3) * 4;
    *(unsigned*)(tb + SWZ16(r, c)     + pos) = hp;   // eh
    *(unsigned*)(tb + SWZ16(r, 8 + c) + pos) = lp;   // el

    double s = (double)v.x * v.x + (double)v.y * v.y;
    #pragma unroll
    for (int off = 16; off > 0; off >>= 1)
        s += __shfl_down_sync(0xffffffffu, s, off);
    if (lane == 0) { g_b32[row] = (float)s; g_counts[row] = 0; }
}

// ---------------------------------------------------------------------------
// Fused convert-x + HMMA distance + top-2 + combine + flag + histogram +
// OUTPUT WRITES. CTA = 128 rows; warps 4x2: wm (32 rows) x wn (64 codes).
// B double-buffered via cp.async; A/B store only unique blocks (xh|xl, eh|el)
// and the k-loop aliases addresses to realize [xh,xl,xh].[eh,eh,el]. After
// the argmin merge the CTA histograms its winners and writes st/qorig/one-hot
// for its 128 rows (provisional idx; the exact pass fixes the rare flips).
// SMEM: bs[1024]f @0, a32s/sIdx @4096, A @5120 (32KB), B0 @37888, B1 @70656.
// ---------------------------------------------------------------------------
#define SM_A  5120
#define SM_B0 37888
#define SM_B1 70656
#define SM_TOTAL 103424

__global__ __launch_bounds__(256, 2) void vq_mma(const float* __restrict__ xall,
                                                 const float* __restrict__ emb,
                                                 float* __restrict__ out) {
    extern __shared__ char smem[];
    float* bs   = (float*)smem;
    float* a32s = (float*)(smem + 4096);
    unsigned sbase = smem_u32(smem);
    int tid  = threadIdx.x;
    int wid  = tid >> 5;
    int lane = tid & 31;
    int l7   = lane & 7;
    int wm   = wid & 3;       // 4 row-groups of 32
    int wn   = wid >> 2;      // 2 code-halves of 64
    int mtile = blockIdx.x;

    // prefetch ntile 0 into B0
    {
        const uint4* src = g_e_swz;
        #pragma unroll
        for (int u = 0; u < 8; u++) {
            int i = u * 256 + tid;
            cp_async16(sbase + SM_B0 + i * 16, src + i);
        }
        CP_COMMIT();
    }

    // Phase 0: bs fill + A convert-fill [xh | xl] + a32
    for (int i = tid; i < K_EMB; i += 256) bs[i] = g_b32[i];
    {
        int r = tid >> 1, h = tid & 1;
        const float4* xr = (const float4*)(xall + ((size_t)(mtile * 128 + r)) * DIM + h * 32);
        double ss = 0.0;
        #pragma unroll
        for (int j = 0; j < 4; j++) {
            float4 f0 = xr[2 * j];
            float4 f1 = xr[2 * j + 1];
            ss += (double)f0.x * f0.x + (double)f0.y * f0.y
                + (double)f0.z * f0.z + (double)f0.w * f0.w
                + (double)f1.x * f1.x + (double)f1.y * f1.y
                + (double)f1.z * f1.z + (double)f1.w * f1.w;
            uint4 hp4, lp4;
            split2(f0.x, f0.y, hp4.x, lp4.x);
            split2(f0.z, f0.w, hp4.y, lp4.y);
            split2(f1.x, f1.y, hp4.z, lp4.z);
            split2(f1.z, f1.w, hp4.w, lp4.w);
            int c = h * 4 + j;
            *(uint4*)(smem + SM_A + SWZ16(r, c))     = hp4;  // xh
            *(uint4*)(smem + SM_A + SWZ16(r, 8 + c)) = lp4;  // xl
        }
        ss += __shfl_xor_sync(0xffffffffu, ss, 1);
        if (h == 0) a32s[r] = (float)ss;
    }

    // ldmatrix base addresses
    int a_sub = ((lane >> 3) & 1) * 8 + l7;
    int a_ch  = (lane >> 4) & 1;
    unsigned abase0 = sbase + SM_A + (wm * 32 + a_sub) * 256;
    unsigned abase1 = abase0 + 16 * 256;
    int b_sub = ((lane >> 4) & 1) * 8 + l7;
    int b_ch  = (lane >> 3) & 1;
    unsigned brow = (wn * 64 + b_sub) * 256;

    int q    = lane >> 2;       // row-within-8 owner
    int cpos = (lane & 3) * 2;  // col pair within n8

    CP_WAIT0();
    __syncthreads();

    float a32r[4];
    #pragma unroll
    for (int m = 0; m < 4; m++) a32r[m] = a32s[wm * 32 + q + m * 8];

    float d1[4], d2[4];
    int   i1[4], i2[4];
    #pragma unroll
    for (int m = 0; m < 4; m++) { d1[m] = 3.4e38f; d2[m] = 3.4e38f; i1[m] = 0; i2[m] = 0; }

    for (int nt = 0; nt < 8; nt++) {
        unsigned bcur = sbase + ((nt & 1) ? SM_B1 : SM_B0);
        if (nt < 7) {
            unsigned bnext = sbase + ((nt & 1) ? SM_B0 : SM_B1);
            const uint4* src = g_e_swz + (nt + 1) * 2048;
            #pragma unroll
            for (int u = 0; u < 8; u++) {
                int i = u * 256 + tid;
                cp_async16(bnext + i * 16, src + i);
            }
            CP_COMMIT();
        }

        unsigned bbase = bcur + brow;

        #pragma unroll
        for (int half = 0; half < 2; half++) {
            float acc[2][4][4];
            #pragma unroll
            for (int t = 0; t < 2; t++)
                #pragma unroll
                for (int j = 0; j < 4; j++) {
                    acc[t][j][0] = 0.f; acc[t][j][1] = 0.f;
                    acc[t][j][2] = 0.f; acc[t][j][3] = 0.f;
                }

            #pragma unroll
            for (int ks = 0; ks < 12; ks++) {
                // A block alias: ks 0-3 -> xh, 4-7 -> xl, 8-11 -> xh
                int pa = (ks < 8) ? ks : (ks - 8);
                int ca = 2 * pa + a_ch;
                unsigned aoff = (((ca & 8) | ((ca & 7) ^ l7)) << 4);
                unsigned af0[4], af1[4];
                ldsm4(af0, abase0 + aoff);
                ldsm4(af1, abase1 + aoff);
                // B block alias: ks 0-3 -> eh, 4-7 -> eh, 8-11 -> el
                int pb = (ks < 4) ? ks : (ks - 4);
                int cb = 2 * pb + b_ch;
                unsigned boff = (((cb & 8) | ((cb & 7) ^ l7)) << 4);
                #pragma unroll
                for (int g = 0; g < 2; g++) {
                    int cg = half * 2 + g;
                    unsigned bf[4];
                    ldsm4(bf, bbase + cg * (16 * 256) + boff);
                    mma_bf16(acc[0][2 * g],     af0, bf);
                    mma_bf16(acc[0][2 * g + 1], af0, bf + 2);
                    mma_bf16(acc[1][2 * g],     af1, bf);
                    mma_bf16(acc[1][2 * g + 1], af1, bf + 2);
                }
            }

            // epilogue: d = fl(fl(a32+b) - 2m); branchy top-2 (updates rare)
            int colbase = nt * 128 + wn * 64 + half * 32;
            #pragma unroll
            for (int j = 0; j < 4; j++) {
                float2 bv = *(float2*)&bs[colbase + j * 8 + cpos];
                int k0 = colbase + j * 8 + cpos;
                #pragma unroll
                for (int t = 0; t < 2; t++) {
                    #pragma unroll
                    for (int rr = 0; rr < 2; rr++) {
                        int m = t * 2 + rr;
                        float ta = a32r[m];
                        float v0 = fmaf(acc[t][j][2 * rr],     -2.0f, __fadd_rn(ta, bv.x));
                        float v1 = fmaf(acc[t][j][2 * rr + 1], -2.0f, __fadd_rn(ta, bv.y));
                        if (v0 < d2[m]) {
                            if (v0 < d1[m]) { d2[m] = d1[m]; i2[m] = i1[m];
                                              d1[m] = v0;    i1[m] = k0; }
                            else            { d2[m] = v0;    i2[m] = k0; }
                        }
                        if (v1 < d2[m]) {
                            if (v1 < d1[m]) { d2[m] = d1[m]; i2[m] = i1[m];
                                              d1[m] = v1;    i1[m] = k0 + 1; }
                            else            { d2[m] = v1;    i2[m] = k0 + 1; }
                        }
                    }
                }
            }
        }
        CP_WAIT0();
        __syncthreads();
    }

    // candidate pool: per lane, per row: (d1,d2,i1,i2)
    #pragma unroll
    for (int m = 0; m < 4; m++) {
        int row = mtile * 128 + wm * 32 + q + m * 8;
        g_part[(size_t)row * 8 + wn * 4 + (lane & 3)] =
            make_float4(d1[m], d2[m], __int_as_float(i1[m]), __int_as_float(i2[m]));
    }

    // quad merge (lanes sharing a row); lowest-index tie-break
    #pragma unroll
    for (int off = 1; off <= 2; off <<= 1) {
        #pragma unroll
        for (int m = 0; m < 4; m++) {
            float od1 = __shfl_xor_sync(0xffffffffu, d1[m], off);
            int   oi1 = __shfl_xor_sync(0xffffffffu, i1[m], off);
            float od2 = __shfl_xor_sync(0xffffffffu, d2[m], off);
            int   oi2 = __shfl_xor_sync(0xffffffffu, i2[m], off);
            if (od1 < d1[m] || (od1 == d1[m] && oi1 < i1[m])) {
                float t = d1[m]; int ti = i1[m];
                d1[m] = od1; i1[m] = oi1;
                if (od2 < t || (od2 == t && oi2 < ti)) { d2[m] = od2; i2[m] = oi2; }
                else                                   { d2[m] = t;   i2[m] = ti; }
            } else if (od1 < d2[m] || (od1 == d2[m] && oi1 < i2[m])) {
                d2[m] = od1; i2[m] = oi1;
            }
        }
    }

    // cross-half merge via smem (reuse B0 region); winners into sIdx;
    // provisional histogram (fixed up by vq_exact on flips)
    __syncthreads();
    float* md1  = (float*)(smem + SM_B0);
    float* md2  = (float*)(smem + SM_B0 + 512);
    int*   mi1  = (int*)  (smem + SM_B0 + 1024);
    int*   sIdx = (int*)  (smem + 4096);
    if (wn == 0 && (lane & 3) == 0) {
        #pragma unroll
        for (int m = 0; m < 4; m++) {
            int rl = wm * 32 + q + m * 8;
            md1[rl] = d1[m]; md2[rl] = d2[m]; mi1[rl] = i1[m];
        }
    }
    __syncthreads();
    if (wn == 1 && (lane & 3) == 0) {
        #pragma unroll
        for (int m = 0; m < 4; m++) {
            int rl  = wm * 32 + q + m * 8;
            int row = mtile * 128 + rl;
            float oa = md1[rl], oa2 = md2[rl];
            int   ia = mi1[rl];
            float D1, D2; int I1;
            if (d1[m] < oa) { D1 = d1[m]; I1 = i1[m]; D2 = fminf(oa, d2[m]); }
            else            { D1 = oa;    I1 = ia;    D2 = fminf(d1[m], oa2); }
            g_idx[row] = I1;
            sIdx[rl]   = I1;
            atomicAdd(&g_counts[I1], 1);
            float thr = a32r[m] * 9.536743e-7f;   // 8 * 2^-23 * a32
            if (!((D2 - D1) > thr)) {
                int pos = atomicAdd(&g_nflag, 1);
                if (pos < N_ROWS) g_flagged[pos] = row;
            }
        }
    }
    __syncthreads();

    // Fused output writes: warp w handles rows [16w, 16w+16) of this mtile.
    // st = fl(x + fl(q - x)), qorig = emb[idx], one-hot row. Streaming stores.
    #pragma unroll 1
    for (int rr = 0; rr < 16; rr++) {
        int rl  = wid * 16 + rr;
        int row = mtile * 128 + rl;
        int idx = sIdx[rl];
        float2 qv = ((const float2*)(emb  + (size_t)idx * DIM))[lane];
        float2 xv = ((const float2*)(xall + (size_t)row * DIM))[lane];
        float2 st;
        st.x = __fadd_rn(xv.x, __fadd_rn(qv.x, -xv.x));
        st.y = __fadd_rn(xv.y, __fadd_rn(qv.y, -xv.y));
        __stcs((float2*)(out + OFF_QST   + (size_t)row * DIM) + lane, st);
        __stcs((float2*)(out + OFF_QORIG + (size_t)row * DIM) + lane, qv);

        float* er = out + OFF_ENC + (size_t)row * K_EMB;
        if (lane < 3) __stcs(er + lane, (lane == idx) ? 1.0f : 0.0f);
        if (lane == 3) __stcs(er + 1023, (idx == 1023) ? 1.0f : 0.0f);
        float4* body = (float4*)(er + 3);   // 16B-aligned
        #pragma unroll
        for (int u = 0; u < 8; u++) {
            int i = u * 32 + lane;
            if (i < 255) {
                int k0 = 3 + i * 4;
                float4 v;
                v.x = (k0     == idx) ? 1.0f : 0.0f;
                v.y = (k0 + 1 == idx) ? 1.0f : 0.0f;
                v.z = (k0 + 2 == idx) ? 1.0f : 0.0f;
                v.w = (k0 + 3 == idx) ? 1.0f : 0.0f;
                __stcs(body + i, v);
            }
        }
    }
}

// ---------------------------------------------------------------------------
// Exact re-rank of flagged rows over the 16 pooled candidates; if the winner
// changes, fix g_idx, the histogram, AND the already-written outputs.
// ---------------------------------------------------------------------------
__global__ __launch_bounds__(256)
void vq_exact(const float* __restrict__ xall, const float* __restrict__ emb,
              float* __restrict__ out) {
    int nf = g_nflag;
    if (nf > N_ROWS) nf = N_ROWS;
    int lane  = threadIdx.x & 31;
    int warp  = (blockIdx.x * blockDim.x + threadIdx.x) >> 5;
    int nwarp = (gridDim.x * blockDim.x) >> 5;

    for (int f = warp; f < nf; f += nwarp) {
        int row  = g_flagged[f];
        int oldi = g_idx[row];
        float bestd = 3.4e38f;
        int   besti = 0x7fffffff;
        if (lane < 16) {
            float4 qq = g_part[(size_t)row * 8 + (lane >> 1)];
            int k = (lane & 1) ? __float_as_int(qq.w) : __float_as_int(qq.z);
            const float* x = xall + (size_t)row * DIM;
            const float* e = emb  + (size_t)k * DIM;
            double ad = 0.0;
            float s = 0.f, c = 0.f;
            #pragma unroll
            for (int j = 0; j < DIM; j++) {
                float xv = __ldg(x + j), ev = __ldg(e + j);
                ad += (double)xv * (double)xv;
                float pr = __fmul_rn(xv, ev);
                float pe = fmaf(xv, ev, -pr);
                float t  = __fadd_rn(s, pr);
                float z  = __fadd_rn(t, -s);
                float se = __fadd_rn(__fadd_rn(s, -__fadd_rn(t, -z)),
                                     __fadd_rn(pr, -z));
                s = t;
                c = __fadd_rn(c, __fadd_rn(pe, se));
            }
            float a32 = (float)ad;
            float m  = __fadd_rn(s, c);
            float t2 = __fadd_rn(a32, g_b32[k]);
            bestd = __fadd_rn(t2, -__fmul_rn(2.0f, m));
            besti = k;
        }
        #pragma unroll
        for (int off = 8; off > 0; off >>= 1) {
            float od = __shfl_down_sync(0xffffffffu, bestd, off);
            int   oi = __shfl_down_sync(0xffffffffu, besti, off);
            if (od < bestd || (od == bestd && oi < besti)) { bestd = od; besti = oi; }
        }
        besti = __shfl_sync(0xffffffffu, besti, 0);

        if (besti != oldi) {
            if (lane == 0) {
                g_idx[row] = besti;
                atomicSub(&g_counts[oldi], 1);
                atomicAdd(&g_counts[besti], 1);
            }
            // fix st / qorig
            float2 qv = ((const float2*)(emb  + (size_t)besti * DIM))[lane];
            float2 xv = ((const float2*)(xall + (size_t)row  * DIM))[lane];
            float2 st;
            st.x = __fadd_rn(xv.x, __fadd_rn(qv.x, -xv.x));
            st.y = __fadd_rn(xv.y, __fadd_rn(qv.y, -xv.y));
            ((float2*)(out + OFF_QST   + (size_t)row * DIM))[lane] = st;
            ((float2*)(out + OFF_QORIG + (size_t)row * DIM))[lane] = qv;
            // fix one-hot
            if (lane == 0) {
                out[OFF_ENC + (size_t)row * K_EMB + oldi]  = 0.0f;
                out[OFF_ENC + (size_t)row * K_EMB + besti] = 1.0f;
            }
        }
    }
}

// ---------------------------------------------------------------------------
// Perplexity in fp32 (reference computes in fp32; MUFU logf/expf, not DFMA).
// ---------------------------------------------------------------------------
__global__ void vq_perplexity(float* __restrict__ out) {
    __shared__ float s[256];
    float local = 0.0f;
    for (int k = threadIdx.x; k < K_EMB; k += 256) {
        float p = (float)g_counts[k] * (1.0f / 131072.0f);
        local += p * logf(p + 1e-10f);
    }
    s[threadIdx.x] = local;
    __syncthreads();
    for (int off = 128; off > 0; off >>= 1) {
        if (threadIdx.x < off) s[threadIdx.x] += s[threadIdx.x + off];
        __syncthreads();
    }
    if (threadIdx.x == 0) out[OFF_PERP] = expf(-s[0]);
}

// ---------------------------------------------------------------------------
extern "C" void kernel_launch(void* const* d_in, const int* in_sizes, int n_in,
                              void* d_out, int out_size) {
    const float* x   = (const float*)d_in[0];
    const float* emb = (const float*)d_in[1];
    float* out = (float*)d_out;

    cudaFuncSetAttribute(vq_mma, cudaFuncAttributeMaxDynamicSharedMemorySize, SM_TOTAL);

    vq_convert_emb<<<128, 256>>>(emb);
    vq_mma<<<1024, 256, SM_TOTAL>>>(x, emb, out);
    vq_exact<<<256, 256>>>(x, emb, out);
    vq_perplexity<<<1, 256>>>(out);
}